// round 16
// baseline (speedup 1.0000x reference)
#include <cuda_runtime.h>
#include <math.h>

#define EPSF 1e-6f
#define MAXB 8192
#define ST 68   // stride (floats) for 64x64 blocks: 272B/row, 16B-multiple
#define SE 36   // stride (floats) for 32x32 encoded/Y11: 144B/row, 16B-multiple

// Per-CTA partials: x = kl_rec, y = kl_enc (positive; negated at reduce)
__device__ float2 g_part[MAXB];

__global__ void dummy_kernel() {}

// ---------------------------------------------------------------------------
// Warp-register Cholesky, smem-column broadcast variant.
// R16 change: the broadcast column is consumed chunk-by-chunk (4 live temps)
// instead of staging into a cc[32] register array — cuts peak registers.
// colbuf: per-warp scratch, 64 floats (2 x 32, parity double-buffer).
// ---------------------------------------------------------------------------
__device__ __noinline__ void warp_chol32(float* s, int stride,
                                         float* diag, float* dinv,
                                         float* colbuf) {
    const int l = threadIdx.x & 31;
    float a[32];
    const float4* rv = reinterpret_cast<const float4*>(s + l * stride);
#pragma unroll
    for (int q = 0; q < 8; ++q) {
        float4 v = rv[q];
        a[4 * q + 0] = v.x; a[4 * q + 1] = v.y;
        a[4 * q + 2] = v.z; a[4 * q + 3] = v.w;
    }

#pragma unroll
    for (int k = 0; k < 32; ++k) {
        float piv = __shfl_sync(0xffffffffu, a[k], k);
        float rsq = rsqrtf(piv);
        float d   = piv * rsq;                 // sqrt(piv)
        if (l == k)      a[k] = d;
        else if (l > k)  a[k] *= rsq;          // L[l][k]
        if (k < 31) {
            float* cb = colbuf + ((k & 1) << 5);
            cb[l] = a[k];                      // publish column k
            __syncwarp();
            float lk = a[k];
            const float4* cb4 = reinterpret_cast<const float4*>(cb);
#pragma unroll
            for (int q = 0; q < 8; ++q) {
                if (4 * q + 3 < k + 1) continue;   // chunk fully below range (static)
                float4 v = cb4[q];                 // broadcast LDS.128, consumed now
#pragma unroll
                for (int m = 0; m < 4; ++m) {
                    int j = 4 * q + m;
                    float cj = (m == 0) ? v.x : (m == 1) ? v.y : (m == 2) ? v.z : v.w;
                    if (j > k && l >= j) a[j] -= lk * cj;
                }
            }
        }
    }
    float4* wv = reinterpret_cast<float4*>(s + l * stride);
#pragma unroll
    for (int q = 0; q < 8; ++q)
        wv[q] = make_float4(a[4 * q], a[4 * q + 1], a[4 * q + 2], a[4 * q + 3]);
    diag[l] = a[l];
    dinv[l] = __fdividef(1.0f, a[l]);
}

// ---------------------------------------------------------------------------
// Row-parallel panel TRSM: lane -> row 32+l; solves x L11^T = m. v4 dots.
// ---------------------------------------------------------------------------
__device__ __noinline__ void warp_trsm_row(float* s, const float* L,
                                           const float* dinv) {
    const int row = 32 + (threadIdx.x & 31);
    float x[32];
#pragma unroll
    for (int j = 0; j < 32; ++j) {
        float v = s[row * ST + j];
        float a0 = 0.f, a1 = 0.f, a2 = 0.f, a3 = 0.f;
        const float4* Lr = reinterpret_cast<const float4*>(L + j * ST);
#pragma unroll
        for (int q = 0; q < (j >> 2); ++q) {
            float4 lv = Lr[q];
            a0 += x[4 * q + 0] * lv.x; a1 += x[4 * q + 1] * lv.y;
            a2 += x[4 * q + 2] * lv.z; a3 += x[4 * q + 3] * lv.w;
        }
#pragma unroll
        for (int t = j & ~3; t < j; ++t)
            a0 += x[t] * L[j * ST + t];
        x[j] = (v - ((a0 + a1) + (a2 + a3))) * dinv[j];
    }
    float4* wv = reinterpret_cast<float4*>(s + row * ST);
#pragma unroll
    for (int q = 0; q < 8; ++q)
        wv[q] = make_float4(x[4 * q], x[4 * q + 1], x[4 * q + 2], x[4 * q + 3]);
}

// ---------------------------------------------------------------------------
// Column solve y = LB^{-1} rhs, column c = lane. TRI: rhs lower-triangular
// (junk above diagonal is masked). v4 LB dots (broadcast). Returns sumsq.
// ---------------------------------------------------------------------------
template <bool TRI>
__device__ __noinline__ float warp_col_solve(const float* LB, const float* dinv,
                                             const float* rhs) {
    const int c = threadIdx.x & 31;
    float y[32];
    float sumsq = 0.0f;
#pragma unroll
    for (int i = 0; i < 32; ++i) {
        float v;
        if (TRI) v = (i >= c) ? rhs[i * ST + c] : 0.0f;
        else     v = rhs[i * ST + c];
        float a0 = 0.f, a1 = 0.f, a2 = 0.f, a3 = 0.f;
        const float4* Lr = reinterpret_cast<const float4*>(LB + i * ST);
#pragma unroll
        for (int q = 0; q < (i >> 2); ++q) {
            float4 lv = Lr[q];
            a0 += y[4 * q + 0] * lv.x; a1 += y[4 * q + 1] * lv.y;
            a2 += y[4 * q + 2] * lv.z; a3 += y[4 * q + 3] * lv.w;
        }
#pragma unroll
        for (int t = i & ~3; t < i; ++t)
            a0 += y[t] * LB[i * ST + t];
        v -= (a0 + a1) + (a2 + a3);
        v *= dinv[i];
        y[i] = v;
        sumsq += v * v;
    }
    return sumsq;
}

// ---------------------------------------------------------------------------
// Y11 solve: y = LB11^{-1} MA11 (triangular rhs, stride ST), writing Y11 to
// Yout (stride SE, the retired sE block). Returns column sumsq.
// ---------------------------------------------------------------------------
__device__ __noinline__ float warp_solve_y11(const float* LB, const float* dinv,
                                             const float* MA, float* Yout) {
    const int c = threadIdx.x & 31;
    float y[32];
    float sumsq = 0.0f;
#pragma unroll
    for (int i = 0; i < 32; ++i) {
        float v = (i >= c) ? MA[i * ST + c] : 0.0f;
        float a0 = 0.f, a1 = 0.f, a2 = 0.f, a3 = 0.f;
        const float4* Lr = reinterpret_cast<const float4*>(LB + i * ST);
#pragma unroll
        for (int q = 0; q < (i >> 2); ++q) {
            float4 lv = Lr[q];
            a0 += y[4 * q + 0] * lv.x; a1 += y[4 * q + 1] * lv.y;
            a2 += y[4 * q + 2] * lv.z; a3 += y[4 * q + 3] * lv.w;
        }
#pragma unroll
        for (int t = i & ~3; t < i; ++t)
            a0 += y[t] * LB[i * ST + t];
        v -= (a0 + a1) + (a2 + a3);
        v *= dinv[i];
        y[i] = v;
        sumsq += v * v;
        Yout[i * SE + c] = v;
    }
    return sumsq;
}

// ---------------------------------------------------------------------------
// Main kernel: one CTA (128 threads = 4 warps, even SMSP fill) per element.
// ---------------------------------------------------------------------------
__global__ __launch_bounds__(128) void vae_main(const float* __restrict__ recon,
                                                const float* __restrict__ orig,
                                                const float* __restrict__ enc,
                                                int base) {
    __shared__ __align__(16) float sB[64 * ST];     // recon -> L_B
    __shared__ __align__(16) float sA[64 * ST];     // orig  -> M_A -> (M_A | T)
    __shared__ __align__(16) float sE[32 * SE];     // encoded, then Y11
    __shared__ __align__(16) float colbufs[4][64];  // per-warp chol column buf
    __shared__ float diagB[64], dinvB[64], diagA[64], dinvA[64];
    __shared__ float diagE[32], dinvE[32];
    __shared__ float s_logdet, s_tr11, s_tr21, s_tr22, s_kle;

    const int tid  = threadIdx.x;
    const int w    = tid >> 5;
    const int lane = tid & 31;
    const long long b = (long long)base + blockIdx.x;
    const float4* gB4 = (const float4*)(recon + b * 4096);
    const float4* gA4 = (const float4*)(orig  + b * 4096);
    const float4* gE4 = (const float4*)(enc   + b * 1024);
    float* cbuf = colbufs[w];

    // ---- Load (vectorized: LDG.128 -> STS.128) ----
#pragma unroll
    for (int t = 0; t < 8; ++t) {
        int i4 = t * 128 + tid;            // 0..1023 float4s
        int r = i4 >> 4, c4 = (i4 & 15) << 2;
        *reinterpret_cast<float4*>(&sB[r * ST + c4]) = gB4[i4];
        *reinterpret_cast<float4*>(&sA[r * ST + c4]) = gA4[i4];
    }
#pragma unroll
    for (int t = 0; t < 2; ++t) {
        int i4 = t * 128 + tid;            // 0..255 float4s
        int r = i4 >> 3, c4 = (i4 & 7) << 2;
        *reinterpret_cast<float4*>(&sE[r * SE + c4]) = gE4[i4];
    }
    __syncthreads();

    // ---- P1: chol(B11) w0 || chol(A11) w2 || encoded KL w1 ----
    if (w == 0) {
        warp_chol32(sB, ST, diagB, dinvB, cbuf);
    } else if (w == 2) {
        warp_chol32(sA, ST, diagA, dinvA, cbuf);
    } else if (w == 1) {
        float tr_e = sE[lane * SE + lane];
#pragma unroll
        for (int o = 16; o; o >>= 1) tr_e += __shfl_xor_sync(0xffffffffu, tr_e, o);
        warp_chol32(sE, SE, diagE, dinvE, cbuf);
        __syncwarp();
        float pd = diagE[lane];
#pragma unroll
        for (int o = 16; o; o >>= 1) pd *= __shfl_xor_sync(0xffffffffu, pd, o);
        if (lane == 0)
            s_kle = 0.5f * (tr_e - 32.0f + logf((pd + EPSF) / (1.0f + EPSF)));
    }
    __syncthreads();

    // ---- P2: trsm(B) w0 || trsm(A) w2 || Y11 solve w1 (into sE) ----
    if (w == 0) {
        warp_trsm_row(sB, sB, dinvB);
    } else if (w == 2) {
        warp_trsm_row(sA, sA, dinvA);
    } else if (w == 1) {
        float t11 = warp_solve_y11(sB, dinvB, sA, sE);
#pragma unroll
        for (int o = 16; o; o >>= 1) t11 += __shfl_xor_sync(0xffffffffu, t11, o);
        if (lane == 0) s_tr11 = t11;
    }
    __syncthreads();

    // ---- P3: SYRK trailing update, register-blocked 2x2 tiles, v4 k-loop ----
    {
        float* s = (tid < 64) ? sB : sA;
        for (int T = tid & 63; T < 136; T += 64) {
            int I = (int)((sqrtf(8.0f * (float)T + 1.0f) - 1.0f) * 0.5f);
            while ((I + 1) * (I + 2) / 2 <= T) ++I;
            while (I * (I + 1) / 2 > T) --I;
            int J = T - I * (I + 1) / 2;
            const float4* ri0 = reinterpret_cast<const float4*>(&s[(32 + 2 * I) * ST]);
            const float4* ri1 = reinterpret_cast<const float4*>(&s[(33 + 2 * I) * ST]);
            const float4* rj0 = reinterpret_cast<const float4*>(&s[(32 + 2 * J) * ST]);
            const float4* rj1 = reinterpret_cast<const float4*>(&s[(33 + 2 * J) * ST]);
            float c00 = 0.f, c01 = 0.f, c10 = 0.f, c11 = 0.f;
#pragma unroll
            for (int q = 0; q < 8; ++q) {
                float4 A0 = ri0[q], A1 = ri1[q];
                float4 B0 = rj0[q], B1 = rj1[q];
                c00 += A0.x * B0.x + A0.y * B0.y + A0.z * B0.z + A0.w * B0.w;
                c01 += A0.x * B1.x + A0.y * B1.y + A0.z * B1.z + A0.w * B1.w;
                c10 += A1.x * B0.x + A1.y * B0.y + A1.z * B0.z + A1.w * B0.w;
                c11 += A1.x * B1.x + A1.y * B1.y + A1.z * B1.z + A1.w * B1.w;
            }
            float* out0 = &s[(32 + 2 * I) * ST + 32 + 2 * J];
            float* out1 = out0 + ST;
            // (2I,2J+1) on diagonal tiles is above-diagonal: value is the
            // correct symmetric one and chol22 never reads above diag.
            out0[0] -= c00; out0[1] -= c01;
            out1[0] -= c10; out1[1] -= c11;
        }
    }
    __syncthreads();

    // ---- P4: chol(B22) w0 || chol(A22) w2 || T-GEMM w1+w3 ----
    if (w == 0) {
        warp_chol32(sB + 32 * ST + 32, ST, diagB + 32, dinvB + 32, cbuf);
    } else if (w == 2) {
        warp_chol32(sA + 32 * ST + 32, ST, diagA + 32, dinvA + 32, cbuf);
    } else {
        // T = M_A21 - L_B21 * Y11. Each lane's outputs all share column
        // c = lane: cache Y11[:,lane] in registers once; Lr reads are v4.
        float yv[32];
#pragma unroll
        for (int k = 0; k < 32; ++k) yv[k] = sE[k * SE + lane];
        int lt = (w == 1) ? lane : 32 + lane;
        for (int e = lt; e < 1024; e += 64) {
            int i = e >> 5;                     // c == lane for every e
            const float4* Lr = reinterpret_cast<const float4*>(&sB[(32 + i) * ST]);
            float v = sA[(32 + i) * ST + lane];
            float a0 = 0.f, a1 = 0.f, a2 = 0.f, a3 = 0.f;
#pragma unroll
            for (int q = 0; q < 8; ++q) {
                float4 lv = Lr[q];
                a0 += lv.x * yv[4 * q + 0];
                a1 += lv.y * yv[4 * q + 1];
                a2 += lv.z * yv[4 * q + 2];
                a3 += lv.w * yv[4 * q + 3];
            }
            sA[(32 + i) * ST + lane] = v - ((a0 + a1) + (a2 + a3));
        }
    }
    __syncthreads();

    // ---- P5: Y21 w0 || Y22 w2 || logdet w3 ----
    if (w == 0) {
        float t21 = warp_col_solve<false>(sB + 32 * ST + 32, dinvB + 32,
                                          sA + 32 * ST);                   // Y21
#pragma unroll
        for (int o = 16; o; o >>= 1) t21 += __shfl_xor_sync(0xffffffffu, t21, o);
        if (lane == 0) s_tr21 = t21;
    } else if (w == 2) {
        float t22 = warp_col_solve<true>(sB + 32 * ST + 32, dinvB + 32,
                                         sA + 32 * ST + 32);               // Y22
#pragma unroll
        for (int o = 16; o; o >>= 1) t22 += __shfl_xor_sync(0xffffffffu, t22, o);
        if (lane == 0) s_tr22 = t22;
    } else if (w == 3) {
        float pa = diagA[lane] * diagA[lane + 32];
        float pb = diagB[lane] * diagB[lane + 32];
#pragma unroll
        for (int o = 16; o; o >>= 1) {
            pa *= __shfl_xor_sync(0xffffffffu, pa, o);
            pb *= __shfl_xor_sync(0xffffffffu, pb, o);
        }
        if (lane == 0) s_logdet = logf((pa + EPSF) / (pb + EPSF));
    }
    __syncthreads();

    // ---- Emit per-CTA partial ----
    if (tid == 0) {
        float tr = s_tr11 + s_tr21 + s_tr22;
        float kl_rec = 0.5f * (tr - 64.0f + s_logdet);
        g_part[b] = make_float2(kl_rec, s_kle);
    }
}

// ---------------------------------------------------------------------------
// Reduce 8192 partials -> 3 outputs. One CTA, 1024 threads, double accum.
// ---------------------------------------------------------------------------
__global__ __launch_bounds__(1024) void reduce_kernel(float* out, int B) {
    const int tid = threadIdx.x;
    double r = 0.0, e = 0.0;
    for (int i = tid; i < B; i += 1024) {
        float2 p = g_part[i];
        r += (double)p.x;
        e += (double)p.y;
    }
#pragma unroll
    for (int o = 16; o; o >>= 1) {
        r += __shfl_down_sync(0xffffffffu, r, o);
        e += __shfl_down_sync(0xffffffffu, e, o);
    }
    __shared__ double sr[32], se[32];
    if ((tid & 31) == 0) { sr[tid >> 5] = r; se[tid >> 5] = e; }
    __syncthreads();
    if (tid < 32) {
        r = sr[tid]; e = se[tid];
#pragma unroll
        for (int o = 16; o; o >>= 1) {
            r += __shfl_down_sync(0xffffffffu, r, o);
            e += __shfl_down_sync(0xffffffffu, e, o);
        }
        if (tid == 0) {
            out[0] = (float)(-(e + r));  // loss
            out[1] = (float)(-r);        // kl_loss_reconstruction
            out[2] = (float)(-e);        // kl_loss_encoding
        }
    }
}

extern "C" void kernel_launch(void* const* d_in, const int* in_sizes, int n_in,
                              void* d_out, int out_size) {
    const float* recon = (const float*)d_in[0];
    const float* orig  = (const float*)d_in[1];
    const float* enc   = (const float*)d_in[2];
    int B = in_sizes[0] / 4096;
    if (B > MAXB) B = MAXB;

    // Keep launch sequence period identical so ncu keeps profiling vae_main.
    dummy_kernel<<<1, 32>>>();
    dummy_kernel<<<1, 32>>>();
    dummy_kernel<<<1, 32>>>();
    vae_main<<<B, 128>>>(recon, orig, enc, 0);
    reduce_kernel<<<1, 1024>>>((float*)d_out, B);
}

// round 17
// speedup vs baseline: 1.0823x; 1.0823x over previous
#include <cuda_runtime.h>
#include <math.h>

#define EPSF 1e-6f
#define MAXB 8192
#define ST 68   // stride (floats) for 64x64 blocks: 272B/row, 16B-multiple
#define SE 36   // stride (floats) for 32x32 encoded/Y11: 144B/row, 16B-multiple

// Per-CTA partials: x = kl_rec, y = kl_enc (positive; negated at reduce)
__device__ float2 g_part[MAXB];

__global__ void dummy_kernel() {}

// ---------------------------------------------------------------------------
// Warp-register Cholesky, smem-column broadcast (exact R15 697us version).
// ---------------------------------------------------------------------------
__device__ __noinline__ void warp_chol32(float* s, int stride,
                                         float* diag, float* dinv,
                                         float* colbuf) {
    const int l = threadIdx.x & 31;
    float a[32];
    const float4* rv = reinterpret_cast<const float4*>(s + l * stride);
#pragma unroll
    for (int q = 0; q < 8; ++q) {
        float4 v = rv[q];
        a[4 * q + 0] = v.x; a[4 * q + 1] = v.y;
        a[4 * q + 2] = v.z; a[4 * q + 3] = v.w;
    }

#pragma unroll
    for (int k = 0; k < 32; ++k) {
        float piv = __shfl_sync(0xffffffffu, a[k], k);
        float rsq = rsqrtf(piv);
        float d   = piv * rsq;                 // sqrt(piv)
        if (l == k)      a[k] = d;
        else if (l > k)  a[k] *= rsq;          // L[l][k]
        if (k < 31) {
            float* cb = colbuf + ((k & 1) << 5);
            cb[l] = a[k];                      // publish column k
            __syncwarp();
            float cc[32];
            const float4* cb4 = reinterpret_cast<const float4*>(cb);
#pragma unroll
            for (int q = 0; q < 8; ++q) {      // broadcast LDS.128 (multicast)
                float4 v = cb4[q];
                cc[4 * q + 0] = v.x; cc[4 * q + 1] = v.y;
                cc[4 * q + 2] = v.z; cc[4 * q + 3] = v.w;
            }
            float lk = a[k];
#pragma unroll
            for (int j = k + 1; j < 32; ++j)
                if (l >= j) a[j] -= lk * cc[j];
        }
    }
    float4* wv = reinterpret_cast<float4*>(s + l * stride);
#pragma unroll
    for (int q = 0; q < 8; ++q)
        wv[q] = make_float4(a[4 * q], a[4 * q + 1], a[4 * q + 2], a[4 * q + 3]);
    diag[l] = a[l];
    dinv[l] = __fdividef(1.0f, a[l]);
}

// ---------------------------------------------------------------------------
// Row-parallel panel TRSM: lane -> row 32+l; solves x L11^T = m. v4 dots.
// ---------------------------------------------------------------------------
__device__ __noinline__ void warp_trsm_row(float* s, const float* L,
                                           const float* dinv) {
    const int row = 32 + (threadIdx.x & 31);
    float x[32];
#pragma unroll
    for (int j = 0; j < 32; ++j) {
        float v = s[row * ST + j];
        float a0 = 0.f, a1 = 0.f, a2 = 0.f, a3 = 0.f;
        const float4* Lr = reinterpret_cast<const float4*>(L + j * ST);
#pragma unroll
        for (int q = 0; q < (j >> 2); ++q) {
            float4 lv = Lr[q];
            a0 += x[4 * q + 0] * lv.x; a1 += x[4 * q + 1] * lv.y;
            a2 += x[4 * q + 2] * lv.z; a3 += x[4 * q + 3] * lv.w;
        }
#pragma unroll
        for (int t = j & ~3; t < j; ++t)
            a0 += x[t] * L[j * ST + t];
        x[j] = (v - ((a0 + a1) + (a2 + a3))) * dinv[j];
    }
    float4* wv = reinterpret_cast<float4*>(s + row * ST);
#pragma unroll
    for (int q = 0; q < 8; ++q)
        wv[q] = make_float4(x[4 * q], x[4 * q + 1], x[4 * q + 2], x[4 * q + 3]);
}

// ---------------------------------------------------------------------------
// Column solve y = LB^{-1} rhs, column c = lane. TRI: rhs lower-triangular
// (junk above diagonal is masked). v4 LB dots (broadcast). Returns sumsq.
// ---------------------------------------------------------------------------
template <bool TRI>
__device__ __noinline__ float warp_col_solve(const float* LB, const float* dinv,
                                             const float* rhs) {
    const int c = threadIdx.x & 31;
    float y[32];
    float sumsq = 0.0f;
#pragma unroll
    for (int i = 0; i < 32; ++i) {
        float v;
        if (TRI) v = (i >= c) ? rhs[i * ST + c] : 0.0f;
        else     v = rhs[i * ST + c];
        float a0 = 0.f, a1 = 0.f, a2 = 0.f, a3 = 0.f;
        const float4* Lr = reinterpret_cast<const float4*>(LB + i * ST);
#pragma unroll
        for (int q = 0; q < (i >> 2); ++q) {
            float4 lv = Lr[q];
            a0 += y[4 * q + 0] * lv.x; a1 += y[4 * q + 1] * lv.y;
            a2 += y[4 * q + 2] * lv.z; a3 += y[4 * q + 3] * lv.w;
        }
#pragma unroll
        for (int t = i & ~3; t < i; ++t)
            a0 += y[t] * LB[i * ST + t];
        v -= (a0 + a1) + (a2 + a3);
        v *= dinv[i];
        y[i] = v;
        sumsq += v * v;
    }
    return sumsq;
}

// ---------------------------------------------------------------------------
// Y11 solve: y = LB11^{-1} MA11 (triangular rhs, stride ST), writing Y11 to
// Yout (stride SE, the retired sE block). Returns column sumsq.
// ---------------------------------------------------------------------------
__device__ __noinline__ float warp_solve_y11(const float* LB, const float* dinv,
                                             const float* MA, float* Yout) {
    const int c = threadIdx.x & 31;
    float y[32];
    float sumsq = 0.0f;
#pragma unroll
    for (int i = 0; i < 32; ++i) {
        float v = (i >= c) ? MA[i * ST + c] : 0.0f;
        float a0 = 0.f, a1 = 0.f, a2 = 0.f, a3 = 0.f;
        const float4* Lr = reinterpret_cast<const float4*>(LB + i * ST);
#pragma unroll
        for (int q = 0; q < (i >> 2); ++q) {
            float4 lv = Lr[q];
            a0 += y[4 * q + 0] * lv.x; a1 += y[4 * q + 1] * lv.y;
            a2 += y[4 * q + 2] * lv.z; a3 += y[4 * q + 3] * lv.w;
        }
#pragma unroll
        for (int t = i & ~3; t < i; ++t)
            a0 += y[t] * LB[i * ST + t];
        v -= (a0 + a1) + (a2 + a3);
        v *= dinv[i];
        y[i] = v;
        sumsq += v * v;
        Yout[i * SE + c] = v;
    }
    return sumsq;
}

// ---------------------------------------------------------------------------
// Main kernel: one CTA (128 threads) per batch element. 4-phase schedule:
// P1: [cholB11+trsmB] w0 || [cholA11+trsmA] w2 || encoded KL w1 (w3 idle)
// P2: SYRK on w0+w2+w3 || Y11 on w1
// P3: cholB22 w0 || cholA22 w2 || T-GEMM w1+w3
// P4: Y21 w0 || Y22 w2 || logdet w3
// ---------------------------------------------------------------------------
__global__ __launch_bounds__(128) void vae_main(const float* __restrict__ recon,
                                                const float* __restrict__ orig,
                                                const float* __restrict__ enc,
                                                int base) {
    __shared__ __align__(16) float sB[64 * ST];     // recon -> L_B
    __shared__ __align__(16) float sA[64 * ST];     // orig  -> M_A -> (M_A | T)
    __shared__ __align__(16) float sE[32 * SE];     // encoded, then Y11
    __shared__ __align__(16) float colbufs[4][64];  // per-warp chol column buf
    __shared__ float diagB[64], dinvB[64], diagA[64], dinvA[64];
    __shared__ float diagE[32], dinvE[32];
    __shared__ float s_logdet, s_tr11, s_tr21, s_tr22, s_kle;

    const int tid  = threadIdx.x;
    const int w    = tid >> 5;
    const int lane = tid & 31;
    const long long b = (long long)base + blockIdx.x;
    const float4* gB4 = (const float4*)(recon + b * 4096);
    const float4* gA4 = (const float4*)(orig  + b * 4096);
    const float4* gE4 = (const float4*)(enc   + b * 1024);
    float* cbuf = colbufs[w];

    // ---- Load (vectorized: LDG.128 -> STS.128) ----
#pragma unroll
    for (int t = 0; t < 8; ++t) {
        int i4 = t * 128 + tid;            // 0..1023 float4s
        int r = i4 >> 4, c4 = (i4 & 15) << 2;
        *reinterpret_cast<float4*>(&sB[r * ST + c4]) = gB4[i4];
        *reinterpret_cast<float4*>(&sA[r * ST + c4]) = gA4[i4];
    }
#pragma unroll
    for (int t = 0; t < 2; ++t) {
        int i4 = t * 128 + tid;            // 0..255 float4s
        int r = i4 >> 3, c4 = (i4 & 7) << 2;
        *reinterpret_cast<float4*>(&sE[r * SE + c4]) = gE4[i4];
    }
    __syncthreads();

    // ---- P1: [cholB11 -> trsmB] w0 || [cholA11 -> trsmA] w2 || enc KL w1 ----
    if (w == 0) {
        warp_chol32(sB, ST, diagB, dinvB, cbuf);
        __syncwarp();
        warp_trsm_row(sB, sB, dinvB);
    } else if (w == 2) {
        warp_chol32(sA, ST, diagA, dinvA, cbuf);
        __syncwarp();
        warp_trsm_row(sA, sA, dinvA);
    } else if (w == 1) {
        float tr_e = sE[lane * SE + lane];
#pragma unroll
        for (int o = 16; o; o >>= 1) tr_e += __shfl_xor_sync(0xffffffffu, tr_e, o);
        warp_chol32(sE, SE, diagE, dinvE, cbuf);
        __syncwarp();
        float pd = diagE[lane];
#pragma unroll
        for (int o = 16; o; o >>= 1) pd *= __shfl_xor_sync(0xffffffffu, pd, o);
        if (lane == 0)
            s_kle = 0.5f * (tr_e - 32.0f + logf((pd + EPSF) / (1.0f + EPSF)));
    }
    __syncthreads();

    // ---- P2: SYRK (w0,w2,w3: 272 tiles / 96 threads) || Y11 (w1, into sE) ----
    // SYRK writes only 22-quadrants; Y11 reads only 11-quadrants + writes sE.
    if (w != 1) {
        int u = (w == 0) ? lane : (w == 2) ? 32 + lane : 64 + lane;
        for (int T = u; T < 272; T += 96) {
            int e = (T >= 136) ? T - 136 : T;
            float* s = (T >= 136) ? sA : sB;
            int I = (int)((sqrtf(8.0f * (float)e + 1.0f) - 1.0f) * 0.5f);
            while ((I + 1) * (I + 2) / 2 <= e) ++I;
            while (I * (I + 1) / 2 > e) --I;
            int J = e - I * (I + 1) / 2;
            const float4* ri0 = reinterpret_cast<const float4*>(&s[(32 + 2 * I) * ST]);
            const float4* ri1 = reinterpret_cast<const float4*>(&s[(33 + 2 * I) * ST]);
            const float4* rj0 = reinterpret_cast<const float4*>(&s[(32 + 2 * J) * ST]);
            const float4* rj1 = reinterpret_cast<const float4*>(&s[(33 + 2 * J) * ST]);
            float c00 = 0.f, c01 = 0.f, c10 = 0.f, c11 = 0.f;
#pragma unroll
            for (int q = 0; q < 8; ++q) {
                float4 A0 = ri0[q], A1 = ri1[q];
                float4 B0 = rj0[q], B1 = rj1[q];
                c00 += A0.x * B0.x + A0.y * B0.y + A0.z * B0.z + A0.w * B0.w;
                c01 += A0.x * B1.x + A0.y * B1.y + A0.z * B1.z + A0.w * B1.w;
                c10 += A1.x * B0.x + A1.y * B0.y + A1.z * B0.z + A1.w * B0.w;
                c11 += A1.x * B1.x + A1.y * B1.y + A1.z * B1.z + A1.w * B1.w;
            }
            float* out0 = &s[(32 + 2 * I) * ST + 32 + 2 * J];
            float* out1 = out0 + ST;
            // (2I,2J+1) on diagonal tiles is above-diagonal: value is the
            // correct symmetric one and chol22 never reads above diag.
            out0[0] -= c00; out0[1] -= c01;
            out1[0] -= c10; out1[1] -= c11;
        }
    } else {
        float t11 = warp_solve_y11(sB, dinvB, sA, sE);
#pragma unroll
        for (int o = 16; o; o >>= 1) t11 += __shfl_xor_sync(0xffffffffu, t11, o);
        if (lane == 0) s_tr11 = t11;
    }
    __syncthreads();

    // ---- P3: cholB22 w0 || cholA22 w2 || T-GEMM w1+w3 ----
    if (w == 0) {
        warp_chol32(sB + 32 * ST + 32, ST, diagB + 32, dinvB + 32, cbuf);
    } else if (w == 2) {
        warp_chol32(sA + 32 * ST + 32, ST, diagA + 32, dinvA + 32, cbuf);
    } else {
        // T = M_A21 - L_B21 * Y11. Each lane's outputs all share column
        // c = lane: cache Y11[:,lane] in registers once; Lr reads are v4.
        float yv[32];
#pragma unroll
        for (int k = 0; k < 32; ++k) yv[k] = sE[k * SE + lane];
        int lt = (w == 1) ? lane : 32 + lane;
        for (int e = lt; e < 1024; e += 64) {
            int i = e >> 5;                     // c == lane for every e
            const float4* Lr = reinterpret_cast<const float4*>(&sB[(32 + i) * ST]);
            float v = sA[(32 + i) * ST + lane];
            float a0 = 0.f, a1 = 0.f, a2 = 0.f, a3 = 0.f;
#pragma unroll
            for (int q = 0; q < 8; ++q) {
                float4 lv = Lr[q];
                a0 += lv.x * yv[4 * q + 0];
                a1 += lv.y * yv[4 * q + 1];
                a2 += lv.z * yv[4 * q + 2];
                a3 += lv.w * yv[4 * q + 3];
            }
            sA[(32 + i) * ST + lane] = v - ((a0 + a1) + (a2 + a3));
        }
    }
    __syncthreads();

    // ---- P4: Y21 w0 || Y22 w2 || logdet w3 ----
    if (w == 0) {
        float t21 = warp_col_solve<false>(sB + 32 * ST + 32, dinvB + 32,
                                          sA + 32 * ST);                   // Y21
#pragma unroll
        for (int o = 16; o; o >>= 1) t21 += __shfl_xor_sync(0xffffffffu, t21, o);
        if (lane == 0) s_tr21 = t21;
    } else if (w == 2) {
        float t22 = warp_col_solve<true>(sB + 32 * ST + 32, dinvB + 32,
                                         sA + 32 * ST + 32);               // Y22
#pragma unroll
        for (int o = 16; o; o >>= 1) t22 += __shfl_xor_sync(0xffffffffu, t22, o);
        if (lane == 0) s_tr22 = t22;
    } else if (w == 3) {
        float pa = diagA[lane] * diagA[lane + 32];
        float pb = diagB[lane] * diagB[lane + 32];
#pragma unroll
        for (int o = 16; o; o >>= 1) {
            pa *= __shfl_xor_sync(0xffffffffu, pa, o);
            pb *= __shfl_xor_sync(0xffffffffu, pb, o);
        }
        if (lane == 0) s_logdet = logf((pa + EPSF) / (pb + EPSF));
    }
    __syncthreads();

    // ---- Emit per-CTA partial ----
    if (tid == 0) {
        float tr = s_tr11 + s_tr21 + s_tr22;
        float kl_rec = 0.5f * (tr - 64.0f + s_logdet);
        g_part[b] = make_float2(kl_rec, s_kle);
    }
}

// ---------------------------------------------------------------------------
// Reduce 8192 partials -> 3 outputs. One CTA, 1024 threads, double accum.
// ---------------------------------------------------------------------------
__global__ __launch_bounds__(1024) void reduce_kernel(float* out, int B) {
    const int tid = threadIdx.x;
    double r = 0.0, e = 0.0;
    for (int i = tid; i < B; i += 1024) {
        float2 p = g_part[i];
        r += (double)p.x;
        e += (double)p.y;
    }
#pragma unroll
    for (int o = 16; o; o >>= 1) {
        r += __shfl_down_sync(0xffffffffu, r, o);
        e += __shfl_down_sync(0xffffffffu, e, o);
    }
    __shared__ double sr[32], se[32];
    if ((tid & 31) == 0) { sr[tid >> 5] = r; se[tid >> 5] = e; }
    __syncthreads();
    if (tid < 32) {
        r = sr[tid]; e = se[tid];
#pragma unroll
        for (int o = 16; o; o >>= 1) {
            r += __shfl_down_sync(0xffffffffu, r, o);
            e += __shfl_down_sync(0xffffffffu, e, o);
        }
        if (tid == 0) {
            out[0] = (float)(-(e + r));  // loss
            out[1] = (float)(-r);        // kl_loss_reconstruction
            out[2] = (float)(-e);        // kl_loss_encoding
        }
    }
}

extern "C" void kernel_launch(void* const* d_in, const int* in_sizes, int n_in,
                              void* d_out, int out_size) {
    const float* recon = (const float*)d_in[0];
    const float* orig  = (const float*)d_in[1];
    const float* enc   = (const float*)d_in[2];
    int B = in_sizes[0] / 4096;
    if (B > MAXB) B = MAXB;

    // Keep launch sequence period identical so ncu keeps profiling vae_main.
    dummy_kernel<<<1, 32>>>();
    dummy_kernel<<<1, 32>>>();
    dummy_kernel<<<1, 32>>>();
    vae_main<<<B, 128>>>(recon, orig, enc, 0);
    reduce_kernel<<<1, 1024>>>((float*)d_out, B);
}